// round 1
// baseline (speedup 1.0000x reference)
#include <cuda_runtime.h>
#include <math.h>

// ---------------------------------------------------------------------------
// K[i,j] = | prod_d cos((x[i,d]-y[j,d])/2) |
// Identity: cos((a-b)/2) = cos(a/2)cos(b/2) + sin(a/2)sin(b/2)
// Phase 1: precompute per-row cos/sin tables (transposed for coalescing).
// Phase 2: GEMM-style 64x64 tiling, 4x4 register blocking, packed f32x2 math.
// ---------------------------------------------------------------------------

#define MAXROWS 16384
#define MAXD 64

// __device__ globals for scratch (no cudaMalloc allowed anywhere)
__device__ float g_Xc[MAXD * MAXROWS];
__device__ float g_Xs[MAXD * MAXROWS];
__device__ float g_Yc[MAXD * MAXROWS];
__device__ float g_Ys[MAXD * MAXROWS];

// --- packed f32x2 helpers (sm_103a) ---------------------------------------
__device__ __forceinline__ unsigned long long f2_mul(unsigned long long a,
                                                     unsigned long long b) {
    unsigned long long r;
    asm("mul.rn.f32x2 %0, %1, %2;" : "=l"(r) : "l"(a), "l"(b));
    return r;
}
__device__ __forceinline__ unsigned long long f2_fma(unsigned long long a,
                                                     unsigned long long b,
                                                     unsigned long long c) {
    unsigned long long r;
    asm("fma.rn.f32x2 %0, %1, %2, %3;" : "=l"(r) : "l"(a), "l"(b), "l"(c));
    return r;
}
__device__ __forceinline__ unsigned long long f2_pack(float lo, float hi) {
    unsigned long long r;
    asm("mov.b64 %0, {%1, %2};" : "=l"(r) : "r"(__float_as_uint(lo)), "r"(__float_as_uint(hi)));
    return r;
}
__device__ __forceinline__ void f2_unpack(unsigned long long v, float& lo, float& hi) {
    unsigned int a, b;
    asm("mov.b64 {%0, %1}, %2;" : "=r"(a), "=r"(b) : "l"(v));
    lo = __uint_as_float(a);
    hi = __uint_as_float(b);
}

// --- Phase 1: sincos precompute (accurate sincosf; tiny cost) --------------
__global__ void qk_precompute(const float* __restrict__ x,
                              const float* __restrict__ y,
                              int n, int m, int d) {
    int t = blockIdx.x * blockDim.x + threadIdx.x;
    int nx = n * d;
    int total = nx + m * d;
    if (t >= total) return;
    if (t < nx) {
        int i = t / d, k = t % d;
        float s, c;
        sincosf(0.5f * x[t], &s, &c);
        g_Xc[k * n + i] = c;
        g_Xs[k * n + i] = s;
    } else {
        int u = t - nx;
        int j = u / d, k = u % d;
        float s, c;
        sincosf(0.5f * y[u], &s, &c);
        g_Yc[k * m + j] = c;
        g_Ys[k * m + j] = s;
    }
}

// --- Phase 2: tiled pairwise product kernel (D known at compile time) ------
// Block: 256 threads, tile 64x64, each thread computes 4 rows x 4 cols.
template <int D>
__global__ __launch_bounds__(256) void qk_tile(float* __restrict__ out,
                                               int n, int m) {
    // X-side stored DUPLICATED (each value twice) so one LDS.64 returns a
    // ready {v,v} broadcast pair for f32x2 math. Y-side planar: contiguous
    // float2 loads give the packed {y_j, y_j+1} pairs.
    __shared__ float sXc[D][128];
    __shared__ float sXs[D][128];
    __shared__ float sYc[D][64];
    __shared__ float sYs[D][64];

    const int tid = threadIdx.x;
    const int bm0 = blockIdx.y * 64;  // output row base
    const int bn0 = blockIdx.x * 64;  // output col base

    // cooperative tile fill: D*64 values per array, 256 threads
    for (int idx = tid; idx < D * 64; idx += 256) {
        int k = idx >> 6;
        int r = idx & 63;
        int gi = bm0 + r; if (gi >= n) gi = n - 1;
        float xc = g_Xc[k * n + gi];
        float xs = g_Xs[k * n + gi];
        *reinterpret_cast<float2*>(&sXc[k][2 * r]) = make_float2(xc, xc);
        *reinterpret_cast<float2*>(&sXs[k][2 * r]) = make_float2(xs, xs);
        int gj = bn0 + r; if (gj >= m) gj = m - 1;
        sYc[k][r] = g_Yc[k * m + gj];
        sYs[k][r] = g_Ys[k * m + gj];
    }
    __syncthreads();

    const int tx = tid & 15;   // col group: cols j0..j0+3
    const int ty = tid >> 4;   // row group: rows i0..i0+3
    const int i0 = ty * 4;
    const int j0 = tx * 4;

    const unsigned long long ONE2 = f2_pack(1.0f, 1.0f);
    unsigned long long acc[4][2];
#pragma unroll
    for (int ii = 0; ii < 4; ii++) {
        acc[ii][0] = ONE2;
        acc[ii][1] = ONE2;
    }

#pragma unroll
    for (int k = 0; k < D; k++) {
        unsigned long long yc0 = *reinterpret_cast<const unsigned long long*>(&sYc[k][j0]);
        unsigned long long yc1 = *reinterpret_cast<const unsigned long long*>(&sYc[k][j0 + 2]);
        unsigned long long ys0 = *reinterpret_cast<const unsigned long long*>(&sYs[k][j0]);
        unsigned long long ys1 = *reinterpret_cast<const unsigned long long*>(&sYs[k][j0 + 2]);
#pragma unroll
        for (int ii = 0; ii < 4; ii++) {
            unsigned long long xc = *reinterpret_cast<const unsigned long long*>(&sXc[k][2 * (i0 + ii)]);
            unsigned long long xs = *reinterpret_cast<const unsigned long long*>(&sXs[k][2 * (i0 + ii)]);
            unsigned long long t0 = f2_fma(xs, ys0, f2_mul(xc, yc0));
            unsigned long long t1 = f2_fma(xs, ys1, f2_mul(xc, yc1));
            acc[ii][0] = f2_mul(acc[ii][0], t0);
            acc[ii][1] = f2_mul(acc[ii][1], t1);
        }
    }

    // epilogue: abs + store (float4 fast path when fully interior)
    bool interior = (bm0 + 63 < n) && (bn0 + 63 < m) && ((m & 3) == 0);
#pragma unroll
    for (int ii = 0; ii < 4; ii++) {
        float v0, v1, v2, v3;
        f2_unpack(acc[ii][0], v0, v1);
        f2_unpack(acc[ii][1], v2, v3);
        v0 = fabsf(v0); v1 = fabsf(v1); v2 = fabsf(v2); v3 = fabsf(v3);
        int gi = bm0 + i0 + ii;
        int gj = bn0 + j0;
        if (interior) {
            *reinterpret_cast<float4*>(&out[(long long)gi * m + gj]) =
                make_float4(v0, v1, v2, v3);
        } else {
            if (gi < n) {
                if (gj + 0 < m) out[(long long)gi * m + gj + 0] = v0;
                if (gj + 1 < m) out[(long long)gi * m + gj + 1] = v1;
                if (gj + 2 < m) out[(long long)gi * m + gj + 2] = v2;
                if (gj + 3 < m) out[(long long)gi * m + gj + 3] = v3;
            }
        }
    }
}

// --- generic fallback (runtime d) ------------------------------------------
__global__ void qk_generic(float* __restrict__ out, int n, int m, int d) {
    int j = blockIdx.x * blockDim.x + threadIdx.x;
    int i = blockIdx.y;
    if (j >= m || i >= n) return;
    float p = 1.0f;
    for (int k = 0; k < d; k++) {
        p *= g_Xc[k * n + i] * g_Yc[k * m + j] + g_Xs[k * n + i] * g_Ys[k * m + j];
    }
    out[(long long)i * m + j] = fabsf(p);
}

extern "C" void kernel_launch(void* const* d_in, const int* in_sizes, int n_in,
                              void* d_out, int out_size) {
    const float* x = (const float*)d_in[0];
    const float* y = (const float*)d_in[1];
    float* out = (float*)d_out;

    // n*d = s0, m*d = s1, n*m = out_size  =>  d = sqrt(s0*s1/out)
    long long s0 = in_sizes[0], s1 = in_sizes[1];
    int d = (int)(0.5 + sqrt((double)s0 * (double)s1 / (double)out_size));
    if (d < 1) d = 1;
    int n = (int)(s0 / d);
    int m = (int)(s1 / d);

    // Phase 1: precompute cos/sin tables
    {
        int total = (n + m) * d;
        int threads = 256;
        int blocks = (total + threads - 1) / threads;
        qk_precompute<<<blocks, threads>>>(x, y, n, m, d);
    }

    // Phase 2: pairwise product
    if (d == 16) {
        dim3 grid((m + 63) / 64, (n + 63) / 64);
        qk_tile<16><<<grid, 256>>>(out, n, m);
    } else {
        dim3 grid((m + 255) / 256, n);
        qk_generic<<<grid, 256>>>(out, n, m, d);
    }
}